// round 2
// baseline (speedup 1.0000x reference)
#include <cuda_runtime.h>
#include <math.h>

// ---------------- problem constants ----------------
#define NB 4096   // batch

// ---------------- scratch (device globals; no allocs) ----------------
__device__ float g_tw1[32 * 25];          // ternarized conv1 weights
__device__ float g_tw2[64 * 800];         // ternarized conv2 weights [oc][800]
__device__ float g_tw2t[800 * 64];        // transposed: [k][oc]
__device__ float g_twf1[512 * 1024];      // ternarized fc1
__device__ float g_twf2[10 * 512];        // ternarized fc2

__device__ float g_conv1[(size_t)NB * 32 * 576];   // [n][32][24][24]
__device__ float g_ps1[NB * 32];
__device__ float g_pq1[NB * 32];
__device__ float g_pool1[(size_t)NB * 32 * 144];   // [n][32][12][12]
__device__ float g_conv2[(size_t)NB * 64 * 64];    // [n][64][8][8]
__device__ float g_ps2[NB * 64];
__device__ float g_pq2[NB * 64];
__device__ float g_pool2[(size_t)NB * 1024];       // [n][64][4][4] == [n][1024]
__device__ float g_fc1o[(size_t)NB * 512];

__device__ float g_bns1[32], g_bnb1[32];  // BN1 fused scale/shift
__device__ float g_bns2[64], g_bnb2[64];

// ---------------- ternarize (TWN): per-output-channel ----------------
// delta = 0.7*mean(|w|); alpha = mean(|w| where |w|>delta); out = sign*alpha where |w|>delta
__global__ void __launch_bounds__(256) k_ternarize(const float* __restrict__ w,
                                                   int which, int per_ch) {
    float* dst = (which == 0) ? g_tw1 : (which == 1) ? g_tw2
               : (which == 2) ? g_twf1 : g_twf2;
    int ch = blockIdx.x;
    const float* wc = w + (size_t)ch * per_ch;
    float* oc = dst + (size_t)ch * per_ch;
    int tid = threadIdx.x;
    __shared__ float sA[8], sB[8];
    __shared__ float s_delta, s_alpha;

    float s = 0.f;
    for (int i = tid; i < per_ch; i += 256) s += fabsf(wc[i]);
    for (int o = 16; o; o >>= 1) s += __shfl_xor_sync(0xffffffffu, s, o);
    if ((tid & 31) == 0) sA[tid >> 5] = s;
    __syncthreads();
    if (tid == 0) {
        float t = 0.f;
        for (int i = 0; i < 8; i++) t += sA[i];
        s_delta = 0.7f * t / (float)per_ch;
    }
    __syncthreads();
    float delta = s_delta;

    float sa = 0.f, cn = 0.f;
    for (int i = tid; i < per_ch; i += 256) {
        float a = fabsf(wc[i]);
        if (a > delta) { sa += a; cn += 1.f; }
    }
    for (int o = 16; o; o >>= 1) {
        sa += __shfl_xor_sync(0xffffffffu, sa, o);
        cn += __shfl_xor_sync(0xffffffffu, cn, o);
    }
    __syncthreads();
    if ((tid & 31) == 0) { sA[tid >> 5] = sa; sB[tid >> 5] = cn; }
    __syncthreads();
    if (tid == 0) {
        float a = 0.f, c = 0.f;
        for (int i = 0; i < 8; i++) { a += sA[i]; c += sB[i]; }
        s_alpha = a / c;
    }
    __syncthreads();
    float alpha = s_alpha;
    for (int i = tid; i < per_ch; i += 256) {
        float v = wc[i];
        oc[i] = (fabsf(v) > delta) ? copysignf(alpha, v) : 0.f;
    }
}

__global__ void k_transpose_w2() {
    int i = blockIdx.x * 256 + threadIdx.x;
    if (i < 64 * 800) {
        int oc = i / 800, k = i - oc * 800;
        g_tw2t[k * 64 + oc] = g_tw2[i];
    }
}

// ---------------- conv1: [n,1,28,28] -> [n,32,24,24] + per-image BN partials ----------------
__global__ void __launch_bounds__(256) k_conv1(const float* __restrict__ x,
                                               const float* __restrict__ bias) {
    __shared__ float s_x[784];
    __shared__ float s_w[800];
    __shared__ float s_b[32];
    __shared__ float s_rs[8], s_rq[8];
    __shared__ float s_sum[32], s_sq[32];
    int n = blockIdx.x, tid = threadIdx.x;
    for (int i = tid; i < 784; i += 256) s_x[i] = x[(size_t)n * 784 + i];
    for (int i = tid; i < 800; i += 256) s_w[i] = g_tw1[i];
    if (tid < 32) s_b[tid] = bias[tid];
    __syncthreads();
    int lane = tid & 31, wid = tid >> 5;

    for (int ocn = 0; ocn < 32; ocn++) {
        float wr[25];
#pragma unroll
        for (int i = 0; i < 25; i++) wr[i] = s_w[ocn * 25 + i];
        float bs = s_b[ocn];
        float ls = 0.f, lq = 0.f;
        float* outp = &g_conv1[((size_t)n * 32 + ocn) * 576];
        // 288 groups of 2 horizontally-adjacent outputs (register reuse of x)
        for (int g = tid; g < 288; g += 256) {
            int pos = g * 2;
            int oy = pos / 24, ox = pos - oy * 24;
            const float* xp = &s_x[oy * 28 + ox];
            float a0 = bs, a1 = bs;
#pragma unroll
            for (int ky = 0; ky < 5; ky++) {
                float x0 = xp[ky * 28 + 0], x1 = xp[ky * 28 + 1], x2 = xp[ky * 28 + 2];
                float x3 = xp[ky * 28 + 3], x4 = xp[ky * 28 + 4], x5 = xp[ky * 28 + 5];
                a0 += x0 * wr[ky * 5 + 0] + x1 * wr[ky * 5 + 1] + x2 * wr[ky * 5 + 2]
                    + x3 * wr[ky * 5 + 3] + x4 * wr[ky * 5 + 4];
                a1 += x1 * wr[ky * 5 + 0] + x2 * wr[ky * 5 + 1] + x3 * wr[ky * 5 + 2]
                    + x4 * wr[ky * 5 + 3] + x5 * wr[ky * 5 + 4];
            }
            outp[pos] = a0;
            outp[pos + 1] = a1;
            ls += a0 + a1;
            lq += a0 * a0 + a1 * a1;
        }
        for (int o = 16; o; o >>= 1) {
            ls += __shfl_xor_sync(0xffffffffu, ls, o);
            lq += __shfl_xor_sync(0xffffffffu, lq, o);
        }
        if (lane == 0) { s_rs[wid] = ls; s_rq[wid] = lq; }
        __syncthreads();
        if (tid == 0) {
            float a = 0.f, b2 = 0.f;
#pragma unroll
            for (int i = 0; i < 8; i++) { a += s_rs[i]; b2 += s_rq[i]; }
            s_sum[ocn] = a; s_sq[ocn] = b2;
        }
        __syncthreads();
    }
    if (tid < 32) {
        g_ps1[n * 32 + tid] = s_sum[tid];
        g_pq1[n * 32 + tid] = s_sq[tid];
    }
}

// ---------------- BN stats: deterministic tree reduce over per-image partials ----------------
__global__ void __launch_bounds__(256) k_bnstats(int which,
                                                 const float* __restrict__ gamma,
                                                 const float* __restrict__ beta) {
    const int C = (which == 1) ? 32 : 64;
    const float* ps = (which == 1) ? g_ps1 : g_ps2;
    const float* pq = (which == 1) ? g_pq1 : g_pq2;
    float* scale = (which == 1) ? g_bns1 : g_bns2;
    float* shift = (which == 1) ? g_bnb1 : g_bnb2;
    const float inv_count = (which == 1) ? (1.f / (4096.f * 576.f)) : (1.f / (4096.f * 64.f));

    int c = blockIdx.x, tid = threadIdx.x;
    __shared__ float sA[8], sB[8];
    float s = 0.f, q = 0.f;
    for (int i = tid; i < NB; i += 256) { s += ps[i * C + c]; q += pq[i * C + c]; }
    for (int o = 16; o; o >>= 1) {
        s += __shfl_xor_sync(0xffffffffu, s, o);
        q += __shfl_xor_sync(0xffffffffu, q, o);
    }
    if ((tid & 31) == 0) { sA[tid >> 5] = s; sB[tid >> 5] = q; }
    __syncthreads();
    if (tid == 0) {
        float ts = 0.f, tq = 0.f;
        for (int i = 0; i < 8; i++) { ts += sA[i]; tq += sB[i]; }
        float mean = ts * inv_count;
        float var = tq * inv_count - mean * mean;
        float sc = gamma[c] * rsqrtf(var + 1e-5f);
        scale[c] = sc;
        shift[c] = beta[c] - mean * sc;
    }
}

// ---------------- BN + maxpool2x2 + relu ----------------
template <int STAGE>
__global__ void __launch_bounds__(256) k_bnpool() {
    constexpr int C = (STAGE == 1) ? 32 : 64;
    constexpr int HI = (STAGE == 1) ? 24 : 8;
    constexpr int HO = HI / 2;
    const float* in = (STAGE == 1) ? g_conv1 : g_conv2;
    float* out = (STAGE == 1) ? g_pool1 : g_pool2;
    const float* scale = (STAGE == 1) ? g_bns1 : g_bns2;
    const float* shift = (STAGE == 1) ? g_bnb1 : g_bnb2;

    int idx = blockIdx.x * 256 + threadIdx.x;
    constexpr int total = NB * C * HO * HO;
    if (idx >= total) return;
    int x = idx % HO;
    int t = idx / HO;
    int y = t % HO; t /= HO;
    int c = t % C;
    int n = t / C;
    const float* ip = in + (((size_t)n * C + c) * HI + 2 * y) * HI + 2 * x;
    float sc = scale[c], sh = shift[c];
    float v0 = ip[0] * sc + sh;
    float v1 = ip[1] * sc + sh;
    float v2 = ip[HI] * sc + sh;
    float v3 = ip[HI + 1] * sc + sh;
    float m = fmaxf(fmaxf(v0, v1), fmaxf(v2, v3));
    out[idx] = fmaxf(m, 0.f);
}

// ---------------- conv2: implicit-im2col GEMM, 1 image/block ----------------
// M = 64 positions, N = 64 out-channels, K = 800. Thread tile 4 pos x 4 oc.
__global__ void __launch_bounds__(256) k_conv2(const float* __restrict__ bias) {
    __shared__ __align__(16) float s_in[32 * 144];     // 18 KB
    __shared__ __align__(16) float s_w[100 * 64];      // 25.6 KB, [k][oc]
    __shared__ int s_kb[100];
    __shared__ float s_sum[64], s_sq[64];
    __shared__ float s_b[64];

    int n = blockIdx.x, tid = threadIdx.x;
    for (int i = tid; i < 4608; i += 256) s_in[i] = g_pool1[(size_t)n * 4608 + i];
    if (tid < 64) s_b[tid] = bias[tid];

    int tp = tid & 15, tc = tid >> 4;
    int oc0 = tc * 4;
    int pos0 = tp * 4;
    int rowoff = (pos0 >> 3) * 12 + (pos0 & 7);   // oy*12 + ox0 (4 consecutive ox share oy)

    float acc[4][4];
#pragma unroll
    for (int i = 0; i < 4; i++)
#pragma unroll
        for (int j = 0; j < 4; j++) acc[i][j] = 0.f;

    for (int kc = 0; kc < 800; kc += 100) {
        __syncthreads();
        for (int i = tid; i < 6400; i += 256) s_w[i] = g_tw2t[kc * 64 + i];
        if (tid < 100) {
            int k = kc + tid;
            int ic = k / 25;
            int r = k - ic * 25;
            int ky = r / 5;
            int kx = r - ky * 5;
            s_kb[tid] = ic * 144 + ky * 12 + kx;
        }
        __syncthreads();
#pragma unroll 2
        for (int j = 0; j < 100; j++) {
            int kb = s_kb[j];
            float4 w4 = *reinterpret_cast<const float4*>(&s_w[j * 64 + oc0]);
            const float* xp = &s_in[kb + rowoff];
            float a0 = xp[0], a1 = xp[1], a2 = xp[2], a3 = xp[3];
            acc[0][0] += a0 * w4.x; acc[0][1] += a0 * w4.y; acc[0][2] += a0 * w4.z; acc[0][3] += a0 * w4.w;
            acc[1][0] += a1 * w4.x; acc[1][1] += a1 * w4.y; acc[1][2] += a1 * w4.z; acc[1][3] += a1 * w4.w;
            acc[2][0] += a2 * w4.x; acc[2][1] += a2 * w4.y; acc[2][2] += a2 * w4.z; acc[2][3] += a2 * w4.w;
            acc[3][0] += a3 * w4.x; acc[3][1] += a3 * w4.y; acc[3][2] += a3 * w4.z; acc[3][3] += a3 * w4.w;
        }
    }

    // bias + store + BN partials
    float ls[4] = {0.f, 0.f, 0.f, 0.f}, lq[4] = {0.f, 0.f, 0.f, 0.f};
#pragma unroll
    for (int ii = 0; ii < 4; ii++) {
        int pos = pos0 + ii;
#pragma unroll
        for (int jj = 0; jj < 4; jj++) {
            float v = acc[ii][jj] + s_b[oc0 + jj];
            g_conv2[((size_t)n * 64 + oc0 + jj) * 64 + pos] = v;
            ls[jj] += v;
            lq[jj] += v * v;
        }
    }
    // channel oc0+jj is owned by the 16 lanes sharing tc (lanes are a warp half)
#pragma unroll
    for (int jj = 0; jj < 4; jj++) {
        for (int o = 8; o; o >>= 1) {
            ls[jj] += __shfl_xor_sync(0xffffffffu, ls[jj], o);
            lq[jj] += __shfl_xor_sync(0xffffffffu, lq[jj], o);
        }
    }
    if (tp == 0) {
#pragma unroll
        for (int jj = 0; jj < 4; jj++) { s_sum[oc0 + jj] = ls[jj]; s_sq[oc0 + jj] = lq[jj]; }
    }
    __syncthreads();
    if (tid < 64) {
        g_ps2[n * 64 + tid] = s_sum[tid];
        g_pq2[n * 64 + tid] = s_sq[tid];
    }
}

// ---------------- fc1: [4096,1024] @ [512,1024]^T + b, relu ----------------
// BM=64, BN=64, BK=16, 256 threads, 4x4 thread tiles.
__global__ void __launch_bounds__(256) k_fc1(const float* __restrict__ bias) {
    __shared__ __align__(16) float As[16][68];
    __shared__ __align__(16) float Bs[16][68];
    int tid = threadIdx.x;
    int brow = blockIdx.y * 64, bcol = blockIdx.x * 64;
    int ty = tid >> 4, tx = tid & 15;
    int lr = tid >> 2;            // 0..63
    int lk = (tid & 3) * 4;       // 0,4,8,12
    float acc[4][4];
#pragma unroll
    for (int i = 0; i < 4; i++)
#pragma unroll
        for (int j = 0; j < 4; j++) acc[i][j] = 0.f;

    const float* Ab = g_pool2 + (size_t)(brow + lr) * 1024 + lk;
    const float* Bb = g_twf1 + (size_t)(bcol + lr) * 1024 + lk;

    for (int kb = 0; kb < 1024; kb += 16) {
        float4 av = *reinterpret_cast<const float4*>(Ab + kb);
        float4 bv = *reinterpret_cast<const float4*>(Bb + kb);
        __syncthreads();
        As[lk + 0][lr] = av.x; As[lk + 1][lr] = av.y; As[lk + 2][lr] = av.z; As[lk + 3][lr] = av.w;
        Bs[lk + 0][lr] = bv.x; Bs[lk + 1][lr] = bv.y; Bs[lk + 2][lr] = bv.z; Bs[lk + 3][lr] = bv.w;
        __syncthreads();
#pragma unroll
        for (int k = 0; k < 16; k++) {
            float4 a4 = *reinterpret_cast<const float4*>(&As[k][ty * 4]);
            float4 b4 = *reinterpret_cast<const float4*>(&Bs[k][tx * 4]);
            acc[0][0] += a4.x * b4.x; acc[0][1] += a4.x * b4.y; acc[0][2] += a4.x * b4.z; acc[0][3] += a4.x * b4.w;
            acc[1][0] += a4.y * b4.x; acc[1][1] += a4.y * b4.y; acc[1][2] += a4.y * b4.z; acc[1][3] += a4.y * b4.w;
            acc[2][0] += a4.z * b4.x; acc[2][1] += a4.z * b4.y; acc[2][2] += a4.z * b4.z; acc[2][3] += a4.z * b4.w;
            acc[3][0] += a4.w * b4.x; acc[3][1] += a4.w * b4.y; acc[3][2] += a4.w * b4.z; acc[3][3] += a4.w * b4.w;
        }
    }
#pragma unroll
    for (int i = 0; i < 4; i++) {
        int row = brow + ty * 4 + i;
#pragma unroll
        for (int j = 0; j < 4; j++) {
            int col = bcol + tx * 4 + j;
            g_fc1o[(size_t)row * 512 + col] = fmaxf(acc[i][j] + __ldg(&bias[col]), 0.f);
        }
    }
}

// ---------------- fc2: [4096,512] @ [10,512]^T + b -> out ----------------
__global__ void __launch_bounds__(256) k_fc2(const float* __restrict__ bias,
                                             float* __restrict__ out) {
    __shared__ float s_w[5120];
    __shared__ float s_b[10];
    int tid = threadIdx.x;
    for (int i = tid; i < 5120; i += 256) s_w[i] = g_twf2[i];
    if (tid < 10) s_b[tid] = bias[tid];
    __syncthreads();
    int wid = tid >> 5, lane = tid & 31;
    int img = blockIdx.x * 8 + wid;
    const float* xr = g_fc1o + (size_t)img * 512;
    float acc[10];
#pragma unroll
    for (int j = 0; j < 10; j++) acc[j] = 0.f;
    for (int k = lane; k < 512; k += 32) {
        float xv = xr[k];
#pragma unroll
        for (int j = 0; j < 10; j++) acc[j] += xv * s_w[j * 512 + k];
    }
#pragma unroll
    for (int j = 0; j < 10; j++)
        for (int o = 16; o; o >>= 1) acc[j] += __shfl_xor_sync(0xffffffffu, acc[j], o);
    if (lane == 0) {
#pragma unroll
        for (int j = 0; j < 10; j++) out[(size_t)img * 10 + j] = acc[j] + s_b[j];
    }
}

// ---------------- launch ----------------
extern "C" void kernel_launch(void* const* d_in, const int* in_sizes, int n_in,
                              void* d_out, int out_size) {
    const float* x   = (const float*)d_in[0];
    const float* w1  = (const float*)d_in[1];
    const float* b1  = (const float*)d_in[2];
    const float* ga1 = (const float*)d_in[3];
    const float* be1 = (const float*)d_in[4];
    const float* w2  = (const float*)d_in[5];
    const float* b2  = (const float*)d_in[6];
    const float* ga2 = (const float*)d_in[7];
    const float* be2 = (const float*)d_in[8];
    const float* wf1 = (const float*)d_in[9];
    const float* bf1 = (const float*)d_in[10];
    const float* wf2 = (const float*)d_in[11];
    const float* bf2 = (const float*)d_in[12];
    float* out = (float*)d_out;

    k_ternarize<<<32, 256>>>(w1, 0, 25);
    k_ternarize<<<64, 256>>>(w2, 1, 800);
    k_ternarize<<<512, 256>>>(wf1, 2, 1024);
    k_ternarize<<<10, 256>>>(wf2, 3, 512);
    k_transpose_w2<<<200, 256>>>();

    k_conv1<<<NB, 256>>>(x, b1);
    k_bnstats<<<32, 256>>>(1, ga1, be1);
    k_bnpool<1><<<(NB * 32 * 144 + 255) / 256, 256>>>();

    k_conv2<<<NB, 256>>>(b2);
    k_bnstats<<<64, 256>>>(2, ga2, be2);
    k_bnpool<2><<<(NB * 64 * 16 + 255) / 256, 256>>>();

    k_fc1<<<dim3(512 / 64, NB / 64), 256>>>(bf1);
    k_fc2<<<NB / 8, 256>>>(bf2, out);
}

// round 3
// speedup vs baseline: 2.9269x; 2.9269x over previous
#include <cuda_runtime.h>
#include <math.h>

#define NB 4096
typedef unsigned long long u64;

// ---------------- f32x2 helpers ----------------
__device__ __forceinline__ u64 dupf(float v) {
    u64 r; asm("mov.b64 %0, {%1, %1};" : "=l"(r) : "f"(v)); return r;
}
__device__ __forceinline__ u64 pk2(float a, float b) {
    u64 r; asm("mov.b64 %0, {%1, %2};" : "=l"(r) : "f"(a), "f"(b)); return r;
}
__device__ __forceinline__ void ffma2(u64 &d, u64 a, u64 b) {
    asm("fma.rn.f32x2 %0, %1, %2, %0;" : "+l"(d) : "l"(a), "l"(b));
}
__device__ __forceinline__ u64 add2(u64 a, u64 b) {
    u64 r; asm("add.rn.f32x2 %0, %1, %2;" : "=l"(r) : "l"(a), "l"(b)); return r;
}
__device__ __forceinline__ float2 unpk(u64 v) {
    float2 r; asm("mov.b64 {%0, %1}, %2;" : "=f"(r.x), "=f"(r.y) : "l"(v)); return r;
}

// ---------------- scratch ----------------
__device__ float g_tw1t[25 * 32];        // conv1 w [k][oc]
__device__ float g_tw2t[800 * 64];       // conv2 w [k][oc]
__device__ float g_twf1[512 * 1024];     // fc1 w [oc][k]
__device__ float g_twf2[10 * 512];       // fc2 w [oc][k]

__device__ float g_pool1pre[(size_t)NB * 32 * 144];  // pooled pre-BN conv1
__device__ float g_pool2pre[(size_t)NB * 1024];      // pooled pre-BN conv2
__device__ float g_fc1o[(size_t)NB * 512];

__device__ float g_ps1[NB * 32], g_pq1[NB * 32];
__device__ float g_ps2[NB * 64], g_pq2[NB * 64];
__device__ float g_bns1[32], g_bnb1[32];
__device__ float g_bns2[64], g_bnb2[64];

// ---------------- ternarize all four weight tensors, one launch ----------------
__global__ void __launch_bounds__(256) k_ternarize_all(const float* __restrict__ w1,
                                                       const float* __restrict__ w2,
                                                       const float* __restrict__ wf1,
                                                       const float* __restrict__ wf2) {
    int b = blockIdx.x;
    const float* wc; int per, mode, ch;
    if (b < 32)       { ch = b;       wc = w1  + (size_t)ch * 25;   per = 25;   mode = 0; }
    else if (b < 96)  { ch = b - 32;  wc = w2  + (size_t)ch * 800;  per = 800;  mode = 1; }
    else if (b < 608) { ch = b - 96;  wc = wf1 + (size_t)ch * 1024; per = 1024; mode = 2; }
    else              { ch = b - 608; wc = wf2 + (size_t)ch * 512;  per = 512;  mode = 3; }

    int tid = threadIdx.x;
    __shared__ float sA[8], sB[8];
    __shared__ float s_delta, s_alpha;

    float s = 0.f;
    for (int i = tid; i < per; i += 256) s += fabsf(wc[i]);
    for (int o = 16; o; o >>= 1) s += __shfl_xor_sync(0xffffffffu, s, o);
    if ((tid & 31) == 0) sA[tid >> 5] = s;
    __syncthreads();
    if (tid == 0) {
        float t = 0.f;
        for (int i = 0; i < 8; i++) t += sA[i];
        s_delta = 0.7f * t / (float)per;
    }
    __syncthreads();
    float delta = s_delta;

    float sa = 0.f, cn = 0.f;
    for (int i = tid; i < per; i += 256) {
        float a = fabsf(wc[i]);
        if (a > delta) { sa += a; cn += 1.f; }
    }
    for (int o = 16; o; o >>= 1) {
        sa += __shfl_xor_sync(0xffffffffu, sa, o);
        cn += __shfl_xor_sync(0xffffffffu, cn, o);
    }
    __syncthreads();
    if ((tid & 31) == 0) { sA[tid >> 5] = sa; sB[tid >> 5] = cn; }
    __syncthreads();
    if (tid == 0) {
        float a = 0.f, c = 0.f;
        for (int i = 0; i < 8; i++) { a += sA[i]; c += sB[i]; }
        s_alpha = a / c;
    }
    __syncthreads();
    float alpha = s_alpha;
    for (int i = tid; i < per; i += 256) {
        float v = wc[i];
        float o = (fabsf(v) > delta) ? copysignf(alpha, v) : 0.f;
        if (mode == 0)      g_tw1t[i * 32 + ch] = o;
        else if (mode == 1) g_tw2t[i * 64 + ch] = o;
        else if (mode == 2) g_twf1[(size_t)ch * 1024 + i] = o;
        else                g_twf2[ch * 512 + i] = o;
    }
}

// ---------------- conv1 + bias + fused 2x2 maxpool (pre-BN) + BN partials ----------------
// 288 threads: ocg = tid&1 (16 oc each), pos = tid>>1 (144 pooled positions)
__global__ void __launch_bounds__(288, 2) k_conv1(const float* __restrict__ x,
                                                  const float* __restrict__ bias) {
    __shared__ __align__(16) float s_x[784];
    __shared__ __align__(8) float2 s_wd[800];   // dup'd weight pairs [k][oc]
    __shared__ float s_b[32];
    __shared__ float s_psum[9][32], s_psq[9][32];
    int n = blockIdx.x, tid = threadIdx.x;
    for (int i = tid; i < 784; i += 288) s_x[i] = x[(size_t)n * 784 + i];
    for (int i = tid; i < 800; i += 288) { float w = g_tw1t[i]; s_wd[i] = make_float2(w, w); }
    if (tid < 32) s_b[tid] = bias[tid];
    __syncthreads();

    int ocg = tid & 1, pos = tid >> 1;
    int py = pos / 12, px = pos - py * 12;
    int lane = tid & 31, warp = tid >> 5;

    // x pairs: rows 2py..2py+5, cols 2px..2px+5 -> 6 rows x 5 overlapping pairs
    u64 P[6][5];
#pragma unroll
    for (int r = 0; r < 6; r++) {
        const float2* rp = reinterpret_cast<const float2*>(&s_x[(2 * py + r) * 28 + 2 * px]);
        float2 a = rp[0], b = rp[1], c = rp[2];
        P[r][0] = pk2(a.x, a.y);
        P[r][1] = pk2(a.y, b.x);
        P[r][2] = pk2(b.x, b.y);
        P[r][3] = pk2(b.y, c.x);
        P[r][4] = pk2(c.x, c.y);
    }

#pragma unroll 1
    for (int j = 0; j < 16; j++) {
        int oc = ocg * 16 + j;
        u64 bdup = dupf(s_b[oc]);
        u64 acc0 = bdup, acc1 = bdup;   // conv rows 2py, 2py+1; pair = cols (2px, 2px+1)
#pragma unroll
        for (int ky = 0; ky < 5; ky++) {
#pragma unroll
            for (int kx = 0; kx < 5; kx++) {
                u64 w = *reinterpret_cast<const u64*>(&s_wd[(ky * 5 + kx) * 32 + oc]);
                ffma2(acc0, P[ky][kx], w);
                ffma2(acc1, P[ky + 1][kx], w);
            }
        }
        float2 v0 = unpk(acc0), v1 = unpk(acc1);
        float sum = (v0.x + v0.y) + (v1.x + v1.y);
        float sq = v0.x * v0.x + v0.y * v0.y + v1.x * v1.x + v1.y * v1.y;
        float mx = fmaxf(fmaxf(v0.x, v0.y), fmaxf(v1.x, v1.y));
        g_pool1pre[(size_t)n * 4608 + oc * 144 + pos] = mx;
        // reduce over the 16 same-parity lanes (same ocg)
#pragma unroll
        for (int o = 2; o <= 16; o <<= 1) {
            sum += __shfl_xor_sync(0xffffffffu, sum, o);
            sq += __shfl_xor_sync(0xffffffffu, sq, o);
        }
        if (lane < 2) { s_psum[warp][oc] = sum; s_psq[warp][oc] = sq; }
    }
    __syncthreads();
    if (tid < 32) {
        float a = 0.f, q = 0.f;
#pragma unroll
        for (int wv = 0; wv < 9; wv++) { a += s_psum[wv][tid]; q += s_psq[wv][tid]; }
        g_ps1[n * 32 + tid] = a;
        g_pq1[n * 32 + tid] = q;
    }
}

// ---------------- BN stats ----------------
__global__ void __launch_bounds__(256) k_bnstats(int which,
                                                 const float* __restrict__ gamma,
                                                 const float* __restrict__ beta) {
    const int C = (which == 1) ? 32 : 64;
    const float* ps = (which == 1) ? g_ps1 : g_ps2;
    const float* pq = (which == 1) ? g_pq1 : g_pq2;
    float* scale = (which == 1) ? g_bns1 : g_bns2;
    float* shift = (which == 1) ? g_bnb1 : g_bnb2;
    const float inv_count = (which == 1) ? (1.f / (4096.f * 576.f)) : (1.f / (4096.f * 64.f));

    int c = blockIdx.x, tid = threadIdx.x;
    __shared__ float sA[8], sB[8];
    float s = 0.f, q = 0.f;
    for (int i = tid; i < NB; i += 256) { s += ps[i * C + c]; q += pq[i * C + c]; }
    for (int o = 16; o; o >>= 1) {
        s += __shfl_xor_sync(0xffffffffu, s, o);
        q += __shfl_xor_sync(0xffffffffu, q, o);
    }
    if ((tid & 31) == 0) { sA[tid >> 5] = s; sB[tid >> 5] = q; }
    __syncthreads();
    if (tid == 0) {
        float ts = 0.f, tq = 0.f;
        for (int i = 0; i < 8; i++) { ts += sA[i]; tq += sB[i]; }
        float mean = ts * inv_count;
        float var = tq * inv_count - mean * mean;
        float sc = gamma[c] * rsqrtf(var + 1e-5f);
        scale[c] = sc;
        shift[c] = beta[c] - mean * sc;
    }
}

// ---------------- conv2: BN1+relu on load, implicit GEMM, fused pool + BN2 partials ----
// 128 threads: tp = tid&15 (4 positions each), tc = tid>>4 (8 oc each)
__global__ void __launch_bounds__(128) k_conv2(const float* __restrict__ bias) {
    __shared__ __align__(16) float s_in[32 * 144];   // 18 KB, post-BN1
    __shared__ __align__(16) float s_w[100 * 64];    // 25.6 KB [k][oc]
    __shared__ int s_kb[100];
    __shared__ float s_s1[32], s_h1[32];
    __shared__ float s_sum[64], s_sq[64];
    __shared__ __align__(8) float s_b[64];

    int n = blockIdx.x, tid = threadIdx.x;
    if (tid < 32) { s_s1[tid] = g_bns1[tid]; s_h1[tid] = g_bnb1[tid]; }
    if (tid < 64) s_b[tid] = bias[tid];
    __syncthreads();
    {
        const float4* src = reinterpret_cast<const float4*>(&g_pool1pre[(size_t)n * 4608]);
        float4* dst = reinterpret_cast<float4*>(s_in);
        for (int i = tid; i < 1152; i += 128) {
            int c = i / 36;
            float sc = s_s1[c], sh = s_h1[c];
            float4 v = src[i];
            v.x = fmaxf(v.x * sc + sh, 0.f);
            v.y = fmaxf(v.y * sc + sh, 0.f);
            v.z = fmaxf(v.z * sc + sh, 0.f);
            v.w = fmaxf(v.w * sc + sh, 0.f);
            dst[i] = v;
        }
    }

    int tp = tid & 15, tc = tid >> 4;
    int oc0 = tc * 8;
    int rowoff = (tp >> 1) * 12 + (tp & 1) * 4;   // oy*12 + ox0

    u64 acc[4][4] = {};   // [pos i][oc pair p]

    for (int kc = 0; kc < 800; kc += 100) {
        __syncthreads();
        for (int i = tid; i < 1600; i += 128)
            reinterpret_cast<float4*>(s_w)[i] =
                reinterpret_cast<const float4*>(&g_tw2t[kc * 64])[i];
        if (tid < 100) {
            int k = kc + tid;
            int ic = k / 25;
            int r = k - ic * 25;
            int ky = r / 5;
            s_kb[tid] = ic * 144 + ky * 12 + (r - ky * 5);
        }
        __syncthreads();
#pragma unroll 2
        for (int j = 0; j < 100; j++) {
            int kb = s_kb[j];
            const ulonglong2* wq = reinterpret_cast<const ulonglong2*>(&s_w[j * 64 + oc0]);
            ulonglong2 wa = wq[0], wb = wq[1];
            const float* xp = &s_in[kb + rowoff];
            u64 x0 = dupf(xp[0]), x1 = dupf(xp[1]), x2 = dupf(xp[2]), x3 = dupf(xp[3]);
            ffma2(acc[0][0], x0, wa.x); ffma2(acc[0][1], x0, wa.y);
            ffma2(acc[0][2], x0, wb.x); ffma2(acc[0][3], x0, wb.y);
            ffma2(acc[1][0], x1, wa.x); ffma2(acc[1][1], x1, wa.y);
            ffma2(acc[1][2], x1, wb.x); ffma2(acc[1][3], x1, wb.y);
            ffma2(acc[2][0], x2, wa.x); ffma2(acc[2][1], x2, wa.y);
            ffma2(acc[2][2], x2, wb.x); ffma2(acc[2][3], x2, wb.y);
            ffma2(acc[3][0], x3, wa.x); ffma2(acc[3][1], x3, wa.y);
            ffma2(acc[3][2], x3, wb.x); ffma2(acc[3][3], x3, wb.y);
        }
    }

    // epilogue: + bias, pool (horizontal in-thread, vertical via shfl), BN partials
    const ulonglong2* bq = reinterpret_cast<const ulonglong2*>(&s_b[oc0]);
    ulonglong2 bA = bq[0], bB = bq[1];
    u64 bp[4] = {bA.x, bA.y, bB.x, bB.y};
    float su[8], sq[8], hm0[8], hm1[8];
#pragma unroll
    for (int p = 0; p < 4; p++) {
        u64 v0 = add2(acc[0][p], bp[p]);
        u64 v1 = add2(acc[1][p], bp[p]);
        u64 v2 = add2(acc[2][p], bp[p]);
        u64 v3 = add2(acc[3][p], bp[p]);
        float2 f0 = unpk(v0), f1 = unpk(v1), f2 = unpk(v2), f3 = unpk(v3);
        su[2 * p]     = (f0.x + f1.x) + (f2.x + f3.x);
        su[2 * p + 1] = (f0.y + f1.y) + (f2.y + f3.y);
        sq[2 * p]     = f0.x * f0.x + f1.x * f1.x + f2.x * f2.x + f3.x * f3.x;
        sq[2 * p + 1] = f0.y * f0.y + f1.y * f1.y + f2.y * f2.y + f3.y * f3.y;
        hm0[2 * p]     = fmaxf(f0.x, f1.x);
        hm0[2 * p + 1] = fmaxf(f0.y, f1.y);
        hm1[2 * p]     = fmaxf(f2.x, f3.x);
        hm1[2 * p + 1] = fmaxf(f2.y, f3.y);
    }
    // vertical pool partner: tp ^ 2 (adjacent oy)
#pragma unroll
    for (int c = 0; c < 8; c++) {
        float pm0 = fmaxf(hm0[c], __shfl_xor_sync(0xffffffffu, hm0[c], 2));
        float pm1 = fmaxf(hm1[c], __shfl_xor_sync(0xffffffffu, hm1[c], 2));
        if ((tp & 2) == 0) {
            int py = tp >> 2, px0 = (tp & 1) * 2;
            float* op = &g_pool2pre[(size_t)n * 1024 + (oc0 + c) * 16 + py * 4 + px0];
            op[0] = pm0;
            op[1] = pm1;
        }
    }
    // stats: reduce over 16 tp lanes (offsets 1..8 stay within half-warp = same tc)
#pragma unroll
    for (int c = 0; c < 8; c++) {
#pragma unroll
        for (int o = 1; o <= 8; o <<= 1) {
            su[c] += __shfl_xor_sync(0xffffffffu, su[c], o);
            sq[c] += __shfl_xor_sync(0xffffffffu, sq[c], o);
        }
    }
    if (tp == 0) {
#pragma unroll
        for (int c = 0; c < 8; c++) { s_sum[oc0 + c] = su[c]; s_sq[oc0 + c] = sq[c]; }
    }
    __syncthreads();
    if (tid < 64) {
        g_ps2[n * 64 + tid] = s_sum[tid];
        g_pq2[n * 64 + tid] = s_sq[tid];
    }
}

// ---------------- fc1: BN2+relu on load, [4096,1024]x[512,1024]^T + b, relu --------------
// BM=BN=128, BK=16, 256 threads, 8x8 tiles via f32x2
__global__ void __launch_bounds__(256) k_fc1(const float* __restrict__ bias) {
    __shared__ __align__(16) float As[16][128];
    __shared__ __align__(16) float Bs[16][128];
    __shared__ float s_sc[64], s_sh[64];
    int tid = threadIdx.x;
    int brow = blockIdx.y * 128, bcol = blockIdx.x * 128;
    if (tid < 64) { s_sc[tid] = g_bns2[tid]; s_sh[tid] = g_bnb2[tid]; }
    int ty = tid >> 4, tx = tid & 15;
    int lr = tid >> 1;            // 0..127
    int lk = (tid & 1) * 8;       // 0 or 8
    u64 acc[8][4] = {};

    const float* Ab = g_pool2pre + (size_t)(brow + lr) * 1024 + lk;
    const float* Bb = g_twf1 + (size_t)(bcol + lr) * 1024 + lk;
    __syncthreads();

    for (int kb = 0; kb < 1024; kb += 16) {
        float4 a0 = *reinterpret_cast<const float4*>(Ab + kb);
        float4 a1 = *reinterpret_cast<const float4*>(Ab + kb + 4);
        float4 b0 = *reinterpret_cast<const float4*>(Bb + kb);
        float4 b1 = *reinterpret_cast<const float4*>(Bb + kb + 4);
        float sc = s_sc[kb >> 4], sh = s_sh[kb >> 4];
        a0.x = fmaxf(a0.x * sc + sh, 0.f); a0.y = fmaxf(a0.y * sc + sh, 0.f);
        a0.z = fmaxf(a0.z * sc + sh, 0.f); a0.w = fmaxf(a0.w * sc + sh, 0.f);
        a1.x = fmaxf(a1.x * sc + sh, 0.f); a1.y = fmaxf(a1.y * sc + sh, 0.f);
        a1.z = fmaxf(a1.z * sc + sh, 0.f); a1.w = fmaxf(a1.w * sc + sh, 0.f);
        __syncthreads();
        As[lk + 0][lr] = a0.x; As[lk + 1][lr] = a0.y; As[lk + 2][lr] = a0.z; As[lk + 3][lr] = a0.w;
        As[lk + 4][lr] = a1.x; As[lk + 5][lr] = a1.y; As[lk + 6][lr] = a1.z; As[lk + 7][lr] = a1.w;
        Bs[lk + 0][lr] = b0.x; Bs[lk + 1][lr] = b0.y; Bs[lk + 2][lr] = b0.z; Bs[lk + 3][lr] = b0.w;
        Bs[lk + 4][lr] = b1.x; Bs[lk + 5][lr] = b1.y; Bs[lk + 6][lr] = b1.z; Bs[lk + 7][lr] = b1.w;
        __syncthreads();
#pragma unroll
        for (int k = 0; k < 16; k++) {
            float4 av0 = *reinterpret_cast<const float4*>(&As[k][ty * 8]);
            float4 av1 = *reinterpret_cast<const float4*>(&As[k][ty * 8 + 4]);
            ulonglong2 bq0 = *reinterpret_cast<const ulonglong2*>(&Bs[k][tx * 8]);
            ulonglong2 bq1 = *reinterpret_cast<const ulonglong2*>(&Bs[k][tx * 8 + 4]);
            u64 bp0 = bq0.x, bp1 = bq0.y, bp2 = bq1.x, bp3 = bq1.y;
            u64 ad[8];
            ad[0] = dupf(av0.x); ad[1] = dupf(av0.y); ad[2] = dupf(av0.z); ad[3] = dupf(av0.w);
            ad[4] = dupf(av1.x); ad[5] = dupf(av1.y); ad[6] = dupf(av1.z); ad[7] = dupf(av1.w);
#pragma unroll
            for (int i = 0; i < 8; i++) {
                ffma2(acc[i][0], ad[i], bp0);
                ffma2(acc[i][1], ad[i], bp1);
                ffma2(acc[i][2], ad[i], bp2);
                ffma2(acc[i][3], ad[i], bp3);
            }
        }
    }
#pragma unroll
    for (int i = 0; i < 8; i++) {
        int row = brow + ty * 8 + i;
#pragma unroll
        for (int p = 0; p < 4; p++) {
            int col = bcol + tx * 8 + 2 * p;
            float2 v = unpk(acc[i][p]);
            g_fc1o[(size_t)row * 512 + col]     = fmaxf(v.x + __ldg(&bias[col]), 0.f);
            g_fc1o[(size_t)row * 512 + col + 1] = fmaxf(v.y + __ldg(&bias[col + 1]), 0.f);
        }
    }
}

// ---------------- fc2 ----------------
__global__ void __launch_bounds__(256) k_fc2(const float* __restrict__ bias,
                                             float* __restrict__ out) {
    __shared__ float s_w[5120];
    __shared__ float s_b[10];
    int tid = threadIdx.x;
    for (int i = tid; i < 5120; i += 256) s_w[i] = g_twf2[i];
    if (tid < 10) s_b[tid] = bias[tid];
    __syncthreads();
    int wid = tid >> 5, lane = tid & 31;
    int img = blockIdx.x * 8 + wid;
    const float* xr = g_fc1o + (size_t)img * 512;
    float acc[10];
#pragma unroll
    for (int j = 0; j < 10; j++) acc[j] = 0.f;
    for (int k = lane; k < 512; k += 32) {
        float xv = xr[k];
#pragma unroll
        for (int j = 0; j < 10; j++) acc[j] += xv * s_w[j * 512 + k];
    }
#pragma unroll
    for (int j = 0; j < 10; j++)
        for (int o = 16; o; o >>= 1) acc[j] += __shfl_xor_sync(0xffffffffu, acc[j], o);
    if (lane == 0) {
#pragma unroll
        for (int j = 0; j < 10; j++) out[(size_t)img * 10 + j] = acc[j] + s_b[j];
    }
}

// ---------------- launch ----------------
extern "C" void kernel_launch(void* const* d_in, const int* in_sizes, int n_in,
                              void* d_out, int out_size) {
    const float* x   = (const float*)d_in[0];
    const float* w1  = (const float*)d_in[1];
    const float* b1  = (const float*)d_in[2];
    const float* ga1 = (const float*)d_in[3];
    const float* be1 = (const float*)d_in[4];
    const float* w2  = (const float*)d_in[5];
    const float* b2  = (const float*)d_in[6];
    const float* ga2 = (const float*)d_in[7];
    const float* be2 = (const float*)d_in[8];
    const float* wf1 = (const float*)d_in[9];
    const float* bf1 = (const float*)d_in[10];
    const float* wf2 = (const float*)d_in[11];
    const float* bf2 = (const float*)d_in[12];
    float* out = (float*)d_out;

    k_ternarize_all<<<618, 256>>>(w1, w2, wf1, wf2);
    k_conv1<<<NB, 288>>>(x, b1);
    k_bnstats<<<32, 256>>>(1, ga1, be1);
    k_conv2<<<NB, 128>>>(b2);
    k_bnstats<<<64, 256>>>(2, ga2, be2);
    k_fc1<<<dim3(512 / 128, NB / 128), 256>>>(bf1);
    k_fc2<<<NB / 8, 256>>>(bf2, out);
}

// round 4
// speedup vs baseline: 3.2600x; 1.1138x over previous
#include <cuda_runtime.h>
#include <math.h>

#define NB 4096
typedef unsigned long long u64;

// ---------------- f32x2 helpers ----------------
__device__ __forceinline__ u64 dupf(float v) {
    u64 r; asm("mov.b64 %0, {%1, %1};" : "=l"(r) : "f"(v)); return r;
}
__device__ __forceinline__ u64 pk2(float a, float b) {
    u64 r; asm("mov.b64 %0, {%1, %2};" : "=l"(r) : "f"(a), "f"(b)); return r;
}
__device__ __forceinline__ void ffma2(u64 &d, u64 a, u64 b) {
    asm("fma.rn.f32x2 %0, %1, %2, %0;" : "+l"(d) : "l"(a), "l"(b));
}
__device__ __forceinline__ u64 add2(u64 a, u64 b) {
    u64 r; asm("add.rn.f32x2 %0, %1, %2;" : "=l"(r) : "l"(a), "l"(b)); return r;
}
__device__ __forceinline__ float2 unpk(u64 v) {
    float2 r; asm("mov.b64 {%0, %1}, %2;" : "=f"(r.x), "=f"(r.y) : "l"(v)); return r;
}

// ---------------- scratch ----------------
__device__ float g_tw1t[25 * 32];        // conv1 w [k][oc]
__device__ float g_tw2t[800 * 64];       // conv2 w [k][oc]
__device__ float g_twf1[512 * 1024];     // fc1 w [oc][k]
__device__ float g_twf2[10 * 512];       // fc2 w [oc][k]

__device__ float g_pool1pre[(size_t)NB * 32 * 144];  // pooled pre-BN conv1
__device__ float g_pool2pre[(size_t)NB * 1024];      // pooled pre-BN conv2
__device__ float g_fc1o[(size_t)NB * 512];

__device__ float g_ps1[NB * 32], g_pq1[NB * 32];
__device__ float g_ps2[NB * 64], g_pq2[NB * 64];
__device__ float g_bns1[32], g_bnb1[32];
__device__ float g_bns2[64], g_bnb2[64];

// ---------------- ternarize all four weight tensors, one launch ----------------
__global__ void __launch_bounds__(256) k_ternarize_all(const float* __restrict__ w1,
                                                       const float* __restrict__ w2,
                                                       const float* __restrict__ wf1,
                                                       const float* __restrict__ wf2) {
    int b = blockIdx.x;
    const float* wc; int per, mode, ch;
    if (b < 32)       { ch = b;       wc = w1  + (size_t)ch * 25;   per = 25;   mode = 0; }
    else if (b < 96)  { ch = b - 32;  wc = w2  + (size_t)ch * 800;  per = 800;  mode = 1; }
    else if (b < 608) { ch = b - 96;  wc = wf1 + (size_t)ch * 1024; per = 1024; mode = 2; }
    else              { ch = b - 608; wc = wf2 + (size_t)ch * 512;  per = 512;  mode = 3; }

    int tid = threadIdx.x;
    __shared__ float sA[8], sB[8];
    __shared__ float s_delta, s_alpha;

    float s = 0.f;
    for (int i = tid; i < per; i += 256) s += fabsf(wc[i]);
    for (int o = 16; o; o >>= 1) s += __shfl_xor_sync(0xffffffffu, s, o);
    if ((tid & 31) == 0) sA[tid >> 5] = s;
    __syncthreads();
    if (tid == 0) {
        float t = 0.f;
        for (int i = 0; i < 8; i++) t += sA[i];
        s_delta = 0.7f * t / (float)per;
    }
    __syncthreads();
    float delta = s_delta;

    float sa = 0.f, cn = 0.f;
    for (int i = tid; i < per; i += 256) {
        float a = fabsf(wc[i]);
        if (a > delta) { sa += a; cn += 1.f; }
    }
    for (int o = 16; o; o >>= 1) {
        sa += __shfl_xor_sync(0xffffffffu, sa, o);
        cn += __shfl_xor_sync(0xffffffffu, cn, o);
    }
    __syncthreads();
    if ((tid & 31) == 0) { sA[tid >> 5] = sa; sB[tid >> 5] = cn; }
    __syncthreads();
    if (tid == 0) {
        float a = 0.f, c = 0.f;
        for (int i = 0; i < 8; i++) { a += sA[i]; c += sB[i]; }
        s_alpha = a / c;
    }
    __syncthreads();
    float alpha = s_alpha;
    for (int i = tid; i < per; i += 256) {
        float v = wc[i];
        float o = (fabsf(v) > delta) ? copysignf(alpha, v) : 0.f;
        if (mode == 0)      g_tw1t[i * 32 + ch] = o;
        else if (mode == 1) g_tw2t[i * 64 + ch] = o;
        else if (mode == 2) g_twf1[(size_t)ch * 1024 + i] = o;
        else                g_twf2[ch * 512 + i] = o;
    }
}

// ---------------- conv1 + bias + fused 2x2 maxpool (pre-BN) + BN partials ----------------
// 288 threads: ocg = tid&1 (16 oc each), pos = tid>>1 (144 pooled positions)
__global__ void __launch_bounds__(288, 2) k_conv1(const float* __restrict__ x,
                                                  const float* __restrict__ bias) {
    __shared__ __align__(16) float s_x[784];
    __shared__ __align__(8) float2 s_wd[800];   // dup'd weight pairs [k][oc]
    __shared__ float s_b[32];
    __shared__ float s_psum[9][32], s_psq[9][32];
    int n = blockIdx.x, tid = threadIdx.x;
    for (int i = tid; i < 784; i += 288) s_x[i] = x[(size_t)n * 784 + i];
    for (int i = tid; i < 800; i += 288) { float w = g_tw1t[i]; s_wd[i] = make_float2(w, w); }
    if (tid < 32) s_b[tid] = bias[tid];
    __syncthreads();

    int ocg = tid & 1, pos = tid >> 1;
    int py = pos / 12, px = pos - py * 12;
    int lane = tid & 31, warp = tid >> 5;

    // x pairs: rows 2py..2py+5, cols 2px..2px+5 -> 6 rows x 5 overlapping pairs
    u64 P[6][5];
#pragma unroll
    for (int r = 0; r < 6; r++) {
        const float2* rp = reinterpret_cast<const float2*>(&s_x[(2 * py + r) * 28 + 2 * px]);
        float2 a = rp[0], b = rp[1], c = rp[2];
        P[r][0] = pk2(a.x, a.y);
        P[r][1] = pk2(a.y, b.x);
        P[r][2] = pk2(b.x, b.y);
        P[r][3] = pk2(b.y, c.x);
        P[r][4] = pk2(c.x, c.y);
    }

#pragma unroll 1
    for (int j = 0; j < 16; j++) {
        int oc = ocg * 16 + j;
        u64 bdup = dupf(s_b[oc]);
        u64 acc0 = bdup, acc1 = bdup;
#pragma unroll
        for (int ky = 0; ky < 5; ky++) {
#pragma unroll
            for (int kx = 0; kx < 5; kx++) {
                u64 w = *reinterpret_cast<const u64*>(&s_wd[(ky * 5 + kx) * 32 + oc]);
                ffma2(acc0, P[ky][kx], w);
                ffma2(acc1, P[ky + 1][kx], w);
            }
        }
        float2 v0 = unpk(acc0), v1 = unpk(acc1);
        float sum = (v0.x + v0.y) + (v1.x + v1.y);
        float sq = v0.x * v0.x + v0.y * v0.y + v1.x * v1.x + v1.y * v1.y;
        float mx = fmaxf(fmaxf(v0.x, v0.y), fmaxf(v1.x, v1.y));
        g_pool1pre[(size_t)n * 4608 + oc * 144 + pos] = mx;
#pragma unroll
        for (int o = 2; o <= 16; o <<= 1) {
            sum += __shfl_xor_sync(0xffffffffu, sum, o);
            sq += __shfl_xor_sync(0xffffffffu, sq, o);
        }
        if (lane < 2) { s_psum[warp][oc] = sum; s_psq[warp][oc] = sq; }
    }
    __syncthreads();
    if (tid < 32) {
        float a = 0.f, q = 0.f;
#pragma unroll
        for (int wv = 0; wv < 9; wv++) { a += s_psum[wv][tid]; q += s_psq[wv][tid]; }
        g_ps1[n * 32 + tid] = a;
        g_pq1[n * 32 + tid] = q;
    }
}

// ---------------- BN stats ----------------
__global__ void __launch_bounds__(256) k_bnstats(int which,
                                                 const float* __restrict__ gamma,
                                                 const float* __restrict__ beta) {
    const int C = (which == 1) ? 32 : 64;
    const float* ps = (which == 1) ? g_ps1 : g_ps2;
    const float* pq = (which == 1) ? g_pq1 : g_pq2;
    float* scale = (which == 1) ? g_bns1 : g_bns2;
    float* shift = (which == 1) ? g_bnb1 : g_bnb2;
    const float inv_count = (which == 1) ? (1.f / (4096.f * 576.f)) : (1.f / (4096.f * 64.f));

    int c = blockIdx.x, tid = threadIdx.x;
    __shared__ float sA[8], sB[8];
    float s = 0.f, q = 0.f;
    for (int i = tid; i < NB; i += 256) { s += ps[i * C + c]; q += pq[i * C + c]; }
    for (int o = 16; o; o >>= 1) {
        s += __shfl_xor_sync(0xffffffffu, s, o);
        q += __shfl_xor_sync(0xffffffffu, q, o);
    }
    if ((tid & 31) == 0) { sA[tid >> 5] = s; sB[tid >> 5] = q; }
    __syncthreads();
    if (tid == 0) {
        float ts = 0.f, tq = 0.f;
        for (int i = 0; i < 8; i++) { ts += sA[i]; tq += sB[i]; }
        float mean = ts * inv_count;
        float var = tq * inv_count - mean * mean;
        float sc = gamma[c] * rsqrtf(var + 1e-5f);
        scale[c] = sc;
        shift[c] = beta[c] - mean * sc;
    }
}

// ---------------- conv2: BN1+relu on load, implicit GEMM, fused pool + BN2 partials ----
// 128 threads: tp = tid&15 (4 positions), tc = tid>>4 (8 oc).
// s_in rows padded to 13 floats (conflict-free banks); x kept in an 8-wide
// register window per (ic,ky), reused across the 5 kx steps.
#define ROWP 13
#define ICP (12 * ROWP)   // 156 floats per input channel
__global__ void __launch_bounds__(128) k_conv2(const float* __restrict__ bias) {
    __shared__ float s_in[32 * ICP];                 // 19.5 KB, post-BN1, padded
    __shared__ __align__(16) float s_w[100 * 64];    // 25.6 KB [k][oc]
    __shared__ int s_base[20];
    __shared__ float s_s1[32], s_h1[32];
    __shared__ float s_sum[64], s_sq[64];
    __shared__ __align__(8) float s_b[64];

    int n = blockIdx.x, tid = threadIdx.x;
    if (tid < 32) { s_s1[tid] = g_bns1[tid]; s_h1[tid] = g_bnb1[tid]; }
    if (tid < 64) s_b[tid] = bias[tid];
    __syncthreads();
    {
        const float4* src = reinterpret_cast<const float4*>(&g_pool1pre[(size_t)n * 4608]);
        for (int i = tid; i < 1152; i += 128) {
            int c = i / 36;                // input channel (36 float4 per channel)
            int r4 = i - c * 36;           // float4 index within channel: 3 per row
            int row = r4 / 3, c4 = r4 - row * 3;
            float sc = s_s1[c], sh = s_h1[c];
            float4 v = src[i];
            v.x = fmaxf(v.x * sc + sh, 0.f);
            v.y = fmaxf(v.y * sc + sh, 0.f);
            v.z = fmaxf(v.z * sc + sh, 0.f);
            v.w = fmaxf(v.w * sc + sh, 0.f);
            float* d = &s_in[c * ICP + row * ROWP + c4 * 4];
            d[0] = v.x; d[1] = v.y; d[2] = v.z; d[3] = v.w;
        }
    }

    int tp = tid & 15, tc = tid >> 4;
    int oc0 = tc * 8;
    int rowoff = (tp >> 1) * ROWP + (tp & 1) * 4;   // oy*13 + ox0

    u64 acc[4][4] = {};   // [pos i][oc pair p]

    for (int kc = 0; kc < 800; kc += 100) {
        __syncthreads();
        for (int i = tid; i < 1600; i += 128)
            reinterpret_cast<float4*>(s_w)[i] =
                reinterpret_cast<const float4*>(&g_tw2t[kc * 64])[i];
        if (tid < 20) {
            int k0 = kc + tid * 5;         // start of a (ic,ky) row of 5 kx
            int ic = k0 / 25;
            int ky = (k0 - ic * 25) / 5;
            s_base[tid] = ic * ICP + ky * ROWP;
        }
        __syncthreads();
#pragma unroll 1
        for (int t = 0; t < 20; t++) {
            const float* xr = &s_in[s_base[t] + rowoff];
            float xw[8];
#pragma unroll
            for (int i = 0; i < 8; i++) xw[i] = xr[i];
#pragma unroll
            for (int kx = 0; kx < 5; kx++) {
                const ulonglong2* wq =
                    reinterpret_cast<const ulonglong2*>(&s_w[(t * 5 + kx) * 64 + oc0]);
                ulonglong2 wa = wq[0], wb = wq[1];
                u64 x0 = dupf(xw[kx]), x1 = dupf(xw[kx + 1]);
                u64 x2 = dupf(xw[kx + 2]), x3 = dupf(xw[kx + 3]);
                ffma2(acc[0][0], x0, wa.x); ffma2(acc[0][1], x0, wa.y);
                ffma2(acc[0][2], x0, wb.x); ffma2(acc[0][3], x0, wb.y);
                ffma2(acc[1][0], x1, wa.x); ffma2(acc[1][1], x1, wa.y);
                ffma2(acc[1][2], x1, wb.x); ffma2(acc[1][3], x1, wb.y);
                ffma2(acc[2][0], x2, wa.x); ffma2(acc[2][1], x2, wa.y);
                ffma2(acc[2][2], x2, wb.x); ffma2(acc[2][3], x2, wb.y);
                ffma2(acc[3][0], x3, wa.x); ffma2(acc[3][1], x3, wa.y);
                ffma2(acc[3][2], x3, wb.x); ffma2(acc[3][3], x3, wb.y);
            }
        }
    }

    // epilogue: + bias, pool (horizontal in-thread, vertical via shfl), BN partials
    const ulonglong2* bq = reinterpret_cast<const ulonglong2*>(&s_b[oc0]);
    ulonglong2 bA = bq[0], bB = bq[1];
    u64 bp[4] = {bA.x, bA.y, bB.x, bB.y};
    float su[8], sq[8], hm0[8], hm1[8];
#pragma unroll
    for (int p = 0; p < 4; p++) {
        u64 v0 = add2(acc[0][p], bp[p]);
        u64 v1 = add2(acc[1][p], bp[p]);
        u64 v2 = add2(acc[2][p], bp[p]);
        u64 v3 = add2(acc[3][p], bp[p]);
        float2 f0 = unpk(v0), f1 = unpk(v1), f2 = unpk(v2), f3 = unpk(v3);
        su[2 * p]     = (f0.x + f1.x) + (f2.x + f3.x);
        su[2 * p + 1] = (f0.y + f1.y) + (f2.y + f3.y);
        sq[2 * p]     = f0.x * f0.x + f1.x * f1.x + f2.x * f2.x + f3.x * f3.x;
        sq[2 * p + 1] = f0.y * f0.y + f1.y * f1.y + f2.y * f2.y + f3.y * f3.y;
        hm0[2 * p]     = fmaxf(f0.x, f1.x);
        hm0[2 * p + 1] = fmaxf(f0.y, f1.y);
        hm1[2 * p]     = fmaxf(f2.x, f3.x);
        hm1[2 * p + 1] = fmaxf(f2.y, f3.y);
    }
#pragma unroll
    for (int c = 0; c < 8; c++) {
        float pm0 = fmaxf(hm0[c], __shfl_xor_sync(0xffffffffu, hm0[c], 2));
        float pm1 = fmaxf(hm1[c], __shfl_xor_sync(0xffffffffu, hm1[c], 2));
        if ((tp & 2) == 0) {
            int py = tp >> 2, px0 = (tp & 1) * 2;
            float* op = &g_pool2pre[(size_t)n * 1024 + (oc0 + c) * 16 + py * 4 + px0];
            op[0] = pm0;
            op[1] = pm1;
        }
    }
#pragma unroll
    for (int c = 0; c < 8; c++) {
#pragma unroll
        for (int o = 1; o <= 8; o <<= 1) {
            su[c] += __shfl_xor_sync(0xffffffffu, su[c], o);
            sq[c] += __shfl_xor_sync(0xffffffffu, sq[c], o);
        }
    }
    if (tp == 0) {
#pragma unroll
        for (int c = 0; c < 8; c++) { s_sum[oc0 + c] = su[c]; s_sq[oc0 + c] = sq[c]; }
    }
    __syncthreads();
    if (tid < 64) {
        g_ps2[n * 64 + tid] = s_sum[tid];
        g_pq2[n * 64 + tid] = s_sq[tid];
    }
}

// ---------------- fc1: BN2+relu on load, [4096,1024]x[512,1024]^T + b, relu --------------
__global__ void __launch_bounds__(256) k_fc1(const float* __restrict__ bias) {
    __shared__ __align__(16) float As[16][128];
    __shared__ __align__(16) float Bs[16][128];
    __shared__ float s_sc[64], s_sh[64];
    int tid = threadIdx.x;
    int brow = blockIdx.y * 128, bcol = blockIdx.x * 128;
    if (tid < 64) { s_sc[tid] = g_bns2[tid]; s_sh[tid] = g_bnb2[tid]; }
    int ty = tid >> 4, tx = tid & 15;
    int lr = tid >> 1;
    int lk = (tid & 1) * 8;
    u64 acc[8][4] = {};

    const float* Ab = g_pool2pre + (size_t)(brow + lr) * 1024 + lk;
    const float* Bb = g_twf1 + (size_t)(bcol + lr) * 1024 + lk;
    __syncthreads();

    for (int kb = 0; kb < 1024; kb += 16) {
        float4 a0 = *reinterpret_cast<const float4*>(Ab + kb);
        float4 a1 = *reinterpret_cast<const float4*>(Ab + kb + 4);
        float4 b0 = *reinterpret_cast<const float4*>(Bb + kb);
        float4 b1 = *reinterpret_cast<const float4*>(Bb + kb + 4);
        float sc = s_sc[kb >> 4], sh = s_sh[kb >> 4];
        a0.x = fmaxf(a0.x * sc + sh, 0.f); a0.y = fmaxf(a0.y * sc + sh, 0.f);
        a0.z = fmaxf(a0.z * sc + sh, 0.f); a0.w = fmaxf(a0.w * sc + sh, 0.f);
        a1.x = fmaxf(a1.x * sc + sh, 0.f); a1.y = fmaxf(a1.y * sc + sh, 0.f);
        a1.z = fmaxf(a1.z * sc + sh, 0.f); a1.w = fmaxf(a1.w * sc + sh, 0.f);
        __syncthreads();
        As[lk + 0][lr] = a0.x; As[lk + 1][lr] = a0.y; As[lk + 2][lr] = a0.z; As[lk + 3][lr] = a0.w;
        As[lk + 4][lr] = a1.x; As[lk + 5][lr] = a1.y; As[lk + 6][lr] = a1.z; As[lk + 7][lr] = a1.w;
        Bs[lk + 0][lr] = b0.x; Bs[lk + 1][lr] = b0.y; Bs[lk + 2][lr] = b0.z; Bs[lk + 3][lr] = b0.w;
        Bs[lk + 4][lr] = b1.x; Bs[lk + 5][lr] = b1.y; Bs[lk + 6][lr] = b1.z; Bs[lk + 7][lr] = b1.w;
        __syncthreads();
#pragma unroll
        for (int k = 0; k < 16; k++) {
            float4 av0 = *reinterpret_cast<const float4*>(&As[k][ty * 8]);
            float4 av1 = *reinterpret_cast<const float4*>(&As[k][ty * 8 + 4]);
            ulonglong2 bq0 = *reinterpret_cast<const ulonglong2*>(&Bs[k][tx * 8]);
            ulonglong2 bq1 = *reinterpret_cast<const ulonglong2*>(&Bs[k][tx * 8 + 4]);
            u64 bp0 = bq0.x, bp1 = bq0.y, bp2 = bq1.x, bp3 = bq1.y;
            u64 ad[8];
            ad[0] = dupf(av0.x); ad[1] = dupf(av0.y); ad[2] = dupf(av0.z); ad[3] = dupf(av0.w);
            ad[4] = dupf(av1.x); ad[5] = dupf(av1.y); ad[6] = dupf(av1.z); ad[7] = dupf(av1.w);
#pragma unroll
            for (int i = 0; i < 8; i++) {
                ffma2(acc[i][0], ad[i], bp0);
                ffma2(acc[i][1], ad[i], bp1);
                ffma2(acc[i][2], ad[i], bp2);
                ffma2(acc[i][3], ad[i], bp3);
            }
        }
    }
#pragma unroll
    for (int i = 0; i < 8; i++) {
        int row = brow + ty * 8 + i;
#pragma unroll
        for (int p = 0; p < 4; p++) {
            int col = bcol + tx * 8 + 2 * p;
            float2 v = unpk(acc[i][p]);
            g_fc1o[(size_t)row * 512 + col]     = fmaxf(v.x + __ldg(&bias[col]), 0.f);
            g_fc1o[(size_t)row * 512 + col + 1] = fmaxf(v.y + __ldg(&bias[col + 1]), 0.f);
        }
    }
}

// ---------------- fc2 ----------------
__global__ void __launch_bounds__(256) k_fc2(const float* __restrict__ bias,
                                             float* __restrict__ out) {
    __shared__ float s_w[5120];
    __shared__ float s_b[10];
    int tid = threadIdx.x;
    for (int i = tid; i < 5120; i += 256) s_w[i] = g_twf2[i];
    if (tid < 10) s_b[tid] = bias[tid];
    __syncthreads();
    int wid = tid >> 5, lane = tid & 31;
    int img = blockIdx.x * 8 + wid;
    const float* xr = g_fc1o + (size_t)img * 512;
    float acc[10];
#pragma unroll
    for (int j = 0; j < 10; j++) acc[j] = 0.f;
    for (int k = lane; k < 512; k += 32) {
        float xv = xr[k];
#pragma unroll
        for (int j = 0; j < 10; j++) acc[j] += xv * s_w[j * 512 + k];
    }
#pragma unroll
    for (int j = 0; j < 10; j++)
        for (int o = 16; o; o >>= 1) acc[j] += __shfl_xor_sync(0xffffffffu, acc[j], o);
    if (lane == 0) {
#pragma unroll
        for (int j = 0; j < 10; j++) out[(size_t)img * 10 + j] = acc[j] + s_b[j];
    }
}

// ---------------- launch ----------------
extern "C" void kernel_launch(void* const* d_in, const int* in_sizes, int n_in,
                              void* d_out, int out_size) {
    const float* x   = (const float*)d_in[0];
    const float* w1  = (const float*)d_in[1];
    const float* b1  = (const float*)d_in[2];
    const float* ga1 = (const float*)d_in[3];
    const float* be1 = (const float*)d_in[4];
    const float* w2  = (const float*)d_in[5];
    const float* b2  = (const float*)d_in[6];
    const float* ga2 = (const float*)d_in[7];
    const float* be2 = (const float*)d_in[8];
    const float* wf1 = (const float*)d_in[9];
    const float* bf1 = (const float*)d_in[10];
    const float* wf2 = (const float*)d_in[11];
    const float* bf2 = (const float*)d_in[12];
    float* out = (float*)d_out;

    k_ternarize_all<<<618, 256>>>(w1, w2, wf1, wf2);
    k_conv1<<<NB, 288>>>(x, b1);
    k_bnstats<<<32, 256>>>(1, ga1, be1);
    k_conv2<<<NB, 128>>>(b2);
    k_bnstats<<<64, 256>>>(2, ga2, be2);
    k_fc1<<<dim3(512 / 128, NB / 128), 256>>>(bf1);
    k_fc2<<<NB / 8, 256>>>(bf2, out);
}